// round 5
// baseline (speedup 1.0000x reference)
#include <cuda_runtime.h>
#include <cstdint>
#include <math.h>

// Problem constants (fixed by the dataset)
#define NN 100000          // nodes
#define EE 1600000         // edges (max)
#define HF 64              // hidden feats
#define HF3 192            // (D+1)*HF

// ---------------- scratch (device globals; no allocations allowed) ----------
__device__ __align__(128) float g_h [NN * HF];     // MLP output h
__device__ __align__(128) float g_L1[NN * HF];     // L^1 h (also layer-1 scratch)
__device__ __align__(128) float g_agg[NN * HF];    // scatter accumulator
__device__ __align__(128) float g_hf[NN * HF3];    // concatenated features
__device__ float g_dinv[3 * NN];
__device__ int   g_deg [3 * NN];
__device__ unsigned char g_cls[EE];
__device__ unsigned int g_hist[4 * 256];
__device__ int g_cnt[2];                // n_neg, n_pos
__device__ unsigned int g_prefix[4];    // radix-select state (4 targets)
__device__ int g_rank[4];
__device__ double g_frac[2];
__device__ float g_thr[2];              // thr_neg, thr_pos

// ---------------- helpers ----------------------------------------------------
__device__ __forceinline__ unsigned f2u(float f) {
    unsigned u = __float_as_uint(f);
    return (u & 0x80000000u) ? ~u : (u ^ 0x80000000u);
}
__device__ __forceinline__ float u2f(unsigned k) {
    unsigned u = (k & 0x80000000u) ? (k ^ 0x80000000u) : ~k;
    return __uint_as_float(u);
}
__device__ __forceinline__ void red4(float* p, float4 v) {
    asm volatile("red.global.add.v4.f32 [%0], {%1,%2,%3,%4};"
                 :: "l"(p), "f"(v.x), "f"(v.y), "f"(v.z), "f"(v.w) : "memory");
}

// ---------------- init / quantile --------------------------------------------
__global__ void k_init() {
    int t = blockIdx.x * blockDim.x + threadIdx.x;
    int stride = gridDim.x * blockDim.x;
    for (int i = t; i < 4 * 256; i += stride) g_hist[i] = 0;
    for (int i = t; i < 3 * NN; i += stride) g_deg[i] = 0;
    if (t < 2) g_cnt[t] = 0;
}

__global__ void k_count(const float* __restrict__ ep, int E) {
    int t = blockIdx.x * blockDim.x + threadIdx.x;
    int stride = gridDim.x * blockDim.x;
    int cn = 0, cp = 0;
    for (int i = t; i < E; i += stride) {
        float x = ep[i];
        if (x <= 0.f) cn++; else cp++;
    }
    cn = __reduce_add_sync(0xffffffffu, cn);
    cp = __reduce_add_sync(0xffffffffu, cp);
    if ((threadIdx.x & 31) == 0) {
        atomicAdd(&g_cnt[0], cn);
        atomicAdd(&g_cnt[1], cp);
    }
}

__global__ void k_init_select() {
    long long nn = g_cnt[0], np = g_cnt[1];
    double idxn = 0.2 * (double)(nn - 1);
    double fln = floor(idxn);
    g_frac[0] = idxn - fln;
    long long lon = (long long)fln;
    long long hin = lon + 1; if (hin > nn - 1) hin = nn - 1;
    g_rank[0] = (int)lon; g_rank[1] = (int)hin;

    double idxp = 0.8 * (double)(np - 1);
    double flp = floor(idxp);
    g_frac[1] = idxp - flp;
    long long lop = (long long)flp;
    long long hip = lop + 1; if (hip > np - 1) hip = np - 1;
    g_rank[2] = (int)lop; g_rank[3] = (int)hip;

    for (int t = 0; t < 4; t++) g_prefix[t] = 0u;
}

__global__ void k_hist(const float* __restrict__ ep, int E, int shift) {
    __shared__ unsigned sh[1024];
    for (int i = threadIdx.x; i < 1024; i += blockDim.x) sh[i] = 0;
    __syncthreads();
    unsigned hm = (shift == 24) ? 0u : (0xFFFFFFFFu << (shift + 8));
    unsigned p0 = g_prefix[0], p1 = g_prefix[1], p2 = g_prefix[2], p3 = g_prefix[3];
    int t = blockIdx.x * blockDim.x + threadIdx.x;
    int stride = gridDim.x * blockDim.x;
    for (int i = t; i < E; i += stride) {
        float x = ep[i];
        unsigned key = f2u(x);
        unsigned bin = (key >> shift) & 255u;
        unsigned kh = key & hm;
        if (x <= 0.f) {
            if (kh == p0) atomicAdd(&sh[bin], 1u);
            if (kh == p1) atomicAdd(&sh[256 + bin], 1u);
        } else {
            if (kh == p2) atomicAdd(&sh[512 + bin], 1u);
            if (kh == p3) atomicAdd(&sh[768 + bin], 1u);
        }
    }
    __syncthreads();
    for (int i = threadIdx.x; i < 1024; i += blockDim.x)
        if (sh[i]) atomicAdd(&g_hist[i], sh[i]);
}

__global__ void k_pick(int shift) {
    int tid = threadIdx.x;
    if (tid < 4) {
        int r = g_rank[tid];
        unsigned pref = g_prefix[tid];
        const unsigned* h = &g_hist[tid * 256];
        for (int b = 0; b < 256; b++) {
            unsigned c = h[b];
            if ((unsigned)r < c) { pref |= ((unsigned)b << shift); break; }
            r -= (int)c;
        }
        g_prefix[tid] = pref;
        g_rank[tid] = r;
    }
    __syncthreads();
    for (int i = tid; i < 1024; i += blockDim.x) g_hist[i] = 0;
}

__global__ void k_finalize() {
    float vlo = u2f(g_prefix[0]), vhi = u2f(g_prefix[1]);
    g_thr[0] = (float)((double)vlo + g_frac[0] * ((double)vhi - (double)vlo));
    vlo = u2f(g_prefix[2]); vhi = u2f(g_prefix[3]);
    g_thr[1] = (float)((double)vlo + g_frac[1] * ((double)vhi - (double)vlo));
}

// ---------------- classify + degrees -----------------------------------------
__global__ void k_classify(const float* __restrict__ ep, const int* __restrict__ dst, int E) {
    int i = blockIdx.x * blockDim.x + threadIdx.x;
    if (i >= E) return;
    float x = ep[i];
    float tn = g_thr[0], tp = g_thr[1];
    int c = (x > tp) ? 0 : ((x < tn) ? 2 : 1);   // 0=pos, 1=unk, 2=neg
    g_cls[i] = (unsigned char)c;
    atomicAdd(&g_deg[c * NN + dst[i]], 1);
}

__global__ void k_dinv() {
    int i = blockIdx.x * blockDim.x + threadIdx.x;
    if (i >= 3 * NN) return;
    int d = g_deg[i];
    if (d < 1) d = 1;
    g_dinv[i] = 1.0f / sqrtf((float)d);
}

// ---------------- SpMV (scatter with vectorized f32 reductions) --------------
__global__ void k_zero_agg() {
    int t = blockIdx.x * blockDim.x + threadIdx.x;
    int stride = gridDim.x * blockDim.x;
    float4 z = make_float4(0.f, 0.f, 0.f, 0.f);
    for (int i = t; i < NN * (HF / 4); i += stride)
        ((float4*)g_agg)[i] = z;
}

__global__ void __launch_bounds__(256) k_spmv(const float* __restrict__ f,
                       const int* __restrict__ src, const int* __restrict__ dst,
                       int fam, int E) {
    int t = blockIdx.x * blockDim.x + threadIdx.x;
    int lane = t & 15;
    int e = t >> 4;
    if (e >= E) return;
    if (g_cls[e] != (unsigned char)fam) return;   // early-out before index loads
    int s = src[e], d = dst[e];
    float sc = g_dinv[fam * NN + s];
    float4 v = *(const float4*)(f + (size_t)s * HF + lane * 4);
    v.x *= sc; v.y *= sc; v.z *= sc; v.w *= sc;
    red4(g_agg + (size_t)d * HF + lane * 4, v);
}

// L1 = h - agg*dinv
__global__ void k_combine1(int fam) {
    int i = blockIdx.x * blockDim.x + threadIdx.x;
    if (i >= NN * (HF / 4)) return;
    float4 h = ((const float4*)g_h)[i];
    float4 a = ((const float4*)g_agg)[i];
    float dv = g_dinv[fam * NN + (i >> 4)];
    float4 o;
    o.x = h.x - a.x * dv; o.y = h.y - a.y * dv;
    o.z = h.z - a.z * dv; o.w = h.w - a.w * dv;
    ((float4*)g_L1)[i] = o;
}

// slice = c0*h + c1*L1 + c2*(L1 - agg*dinv)
__global__ void k_combine2(int fam, int off4, float c0, float c1, float c2) {
    int i = blockIdx.x * blockDim.x + threadIdx.x;
    if (i >= NN * (HF / 4)) return;
    float4 h = ((const float4*)g_h)[i];
    float4 l1 = ((const float4*)g_L1)[i];
    float4 a = ((const float4*)g_agg)[i];
    float dv = g_dinv[fam * NN + (i >> 4)];
    int row = i >> 4, j4 = i & 15;
    float4 o;
    float l2;
    l2 = l1.x - a.x * dv; o.x = c0 * h.x + c1 * l1.x + c2 * l2;
    l2 = l1.y - a.y * dv; o.y = c0 * h.y + c1 * l1.y + c2 * l2;
    l2 = l1.z - a.z * dv; o.z = c0 * h.z + c1 * l1.z + c2 * l2;
    l2 = l1.w - a.w * dv; o.w = c0 * h.w + c1 * l1.w + c2 * l2;
    ((float4*)g_hf)[(size_t)row * (HF3 / 4) + off4 + j4] = o;
}

// ---------------- GEMM: out = relu(A[M,K] @ W[K,64] + b) ----------------------
template <int K, int KC>
__global__ void __launch_bounds__(256) k_gemm(const float* __restrict__ A, const float* __restrict__ W,
                       const float* __restrict__ bias, float* __restrict__ out, int M) {
    __shared__ float sW[KC * 64];
    __shared__ float sA[16 * K];
    int tid = threadIdx.x;            // 256 threads
    int r = tid >> 4;                 // 0..15 (row within tile)
    int c4 = (tid & 15) * 4;          // 0..60 (col group)
    for (int tile = blockIdx.x * 16; tile < M; tile += gridDim.x * 16) {
        __syncthreads();
        for (int i = tid; i < 16 * K; i += 256)
            sA[i] = A[(size_t)tile * K + i];
        float a0 = 0.f, a1 = 0.f, a2 = 0.f, a3 = 0.f;
        for (int ch = 0; ch < K; ch += KC) {
            __syncthreads();
            for (int i = tid; i < KC * 64; i += 256)
                sW[i] = W[ch * 64 + i];
            __syncthreads();
            #pragma unroll 8
            for (int k = 0; k < KC; k++) {
                float av = sA[r * K + ch + k];
                float4 w = *(const float4*)&sW[k * 64 + c4];
                a0 = fmaf(av, w.x, a0);
                a1 = fmaf(av, w.y, a1);
                a2 = fmaf(av, w.z, a2);
                a3 = fmaf(av, w.w, a3);
            }
        }
        int row = tile + r;
        if (row < M) {
            float4 o;
            o.x = fmaxf(a0 + bias[c4 + 0], 0.f);
            o.y = fmaxf(a1 + bias[c4 + 1], 0.f);
            o.z = fmaxf(a2 + bias[c4 + 2], 0.f);
            o.w = fmaxf(a3 + bias[c4 + 3], 0.f);
            *(float4*)&out[(size_t)row * 64 + c4] = o;
        }
    }
}

// ---------------- launch ------------------------------------------------------
extern "C" void kernel_launch(void* const* d_in, const int* in_sizes, int n_in,
                              void* d_out, int out_size) {
    const float* feat = (const float*)d_in[0];
    const float* ep   = (const float*)d_in[1];
    const int*   src  = (const int*)d_in[2];
    const int*   dst  = (const int*)d_in[3];
    const float* W1   = (const float*)d_in[4];
    const float* b1   = (const float*)d_in[5];
    const float* W2   = (const float*)d_in[6];
    const float* b2   = (const float*)d_in[7];
    const float* W3   = (const float*)d_in[8];
    const float* b3   = (const float*)d_in[9];
    float* out = (float*)d_out;
    int E = in_sizes[1];
    int M = NN;

    float *p_h, *p_L1, *p_hf;
    cudaGetSymbolAddress((void**)&p_h,  g_h);
    cudaGetSymbolAddress((void**)&p_L1, g_L1);
    cudaGetSymbolAddress((void**)&p_hf, g_hf);

    // 1) thresholds via 4-pass radix select (all device-side)
    k_init<<<256, 256>>>();
    k_count<<<512, 256>>>(ep, E);
    k_init_select<<<1, 1>>>();
    for (int shift = 24; shift >= 0; shift -= 8) {
        k_hist<<<1024, 256>>>(ep, E, shift);
        k_pick<<<1, 256>>>(shift);
    }
    k_finalize<<<1, 1>>>();

    // 2) classify edges + degrees + dinv
    k_classify<<<(E + 255) / 256, 256>>>(ep, dst, E);
    k_dinv<<<(3 * NN + 255) / 256, 256>>>();

    // 3) MLP: h = relu(relu(feat@W1+b1)@W2+b2)
    k_gemm<128, 128><<<6250, 256>>>(feat, W1, b1, p_L1, M);
    k_gemm<64, 64><<<6250, 256>>>(p_L1, W2, b2, p_h, M);

    // 4) Laplacian powers per family; theta coefficients folded in.
    // fam 0 = pos -> slice [0:64),   coeffs (0, 0, 0.75)
    // fam 1 = unk -> slice [64:128), coeffs (0, 3, -1.5)
    // fam 2 = neg -> slice [128:192),coeffs (3, -3, 0.75)
    const float C0[3] = {0.f, 0.f, 3.f};
    const float C1[3] = {0.f, 3.f, -3.f};
    const float C2[3] = {0.75f, -1.5f, 0.75f};
    const int OFF4[3] = {0, 16, 32};
    int spmv_blocks = (E * 16 + 255) / 256;
    int elem_blocks = (NN * (HF / 4) + 255) / 256;
    for (int fam = 0; fam < 3; fam++) {
        k_zero_agg<<<2048, 256>>>();
        k_spmv<<<spmv_blocks, 256>>>(p_h, src, dst, fam, E);
        k_combine1<<<elem_blocks, 256>>>(fam);
        k_zero_agg<<<2048, 256>>>();
        k_spmv<<<spmv_blocks, 256>>>(p_L1, src, dst, fam, E);
        k_combine2<<<elem_blocks, 256>>>(fam, OFF4[fam], C0[fam], C1[fam], C2[fam]);
    }

    // 5) out = relu(hfinal @ W3 + b3)
    k_gemm<192, 96><<<6250, 256>>>(p_hf, W3, b3, out, M);
}

// round 6
// speedup vs baseline: 1.4767x; 1.4767x over previous
#include <cuda_runtime.h>
#include <cstdint>
#include <math.h>

#define NN 100000          // nodes
#define EE 1600000         // edges (max)
#define HF 64              // hidden feats
#define HF3 192            // (D+1)*HF
typedef unsigned long long ull;

// ---------------- scratch (device globals; no allocations allowed) ----------
__device__ __align__(128) float g_h  [NN * HF];        // MLP output h
__device__ __align__(128) float g_L1 [3 * NN * HF];    // per-family L^1 h (also layer-1 scratch)
__device__ __align__(128) float g_agg[3 * NN * HF];    // per-family scatter accumulators
__device__ __align__(128) float g_hf [NN * HF3];       // concatenated features
__device__ float g_dinv[3 * NN];
__device__ int   g_deg [3 * NN];
__device__ unsigned char g_cls[EE];
__device__ unsigned int g_hist[4 * 256];
__device__ int g_cnt[2];
__device__ unsigned int g_prefix[4];
__device__ int g_rank[4];
__device__ double g_frac[2];
__device__ float g_thr[2];

// ---------------- helpers ----------------------------------------------------
__device__ __forceinline__ unsigned f2u(float f) {
    unsigned u = __float_as_uint(f);
    return (u & 0x80000000u) ? ~u : (u ^ 0x80000000u);
}
__device__ __forceinline__ float u2f(unsigned k) {
    unsigned u = (k & 0x80000000u) ? (k ^ 0x80000000u) : ~k;
    return __uint_as_float(u);
}
__device__ __forceinline__ void red4(float* p, float4 v) {
    asm volatile("red.global.add.v4.f32 [%0], {%1,%2,%3,%4};"
                 :: "l"(p), "f"(v.x), "f"(v.y), "f"(v.z), "f"(v.w) : "memory");
}
#define FMA2(acc, a, w) asm("fma.rn.f32x2 %0, %1, %2, %0;" : "+l"(acc) : "l"(a), "l"(w))
__device__ __forceinline__ ull packdup(float a) {
    ull r;
    asm("mov.b64 %0, {%1, %1};" : "=l"(r) : "r"(__float_as_uint(a)));
    return r;
}
__device__ __forceinline__ float2 unpack2(ull v) {
    unsigned lo, hi;
    asm("mov.b64 {%0, %1}, %2;" : "=r"(lo), "=r"(hi) : "l"(v));
    return make_float2(__uint_as_float(lo), __uint_as_float(hi));
}

// ---------------- init / quantile --------------------------------------------
__global__ void k_init() {
    int t = blockIdx.x * blockDim.x + threadIdx.x;
    int stride = gridDim.x * blockDim.x;
    for (int i = t; i < 4 * 256; i += stride) g_hist[i] = 0;
    for (int i = t; i < 3 * NN; i += stride) g_deg[i] = 0;
    if (t < 2) g_cnt[t] = 0;
}

__global__ void k_count(const float* __restrict__ ep, int E) {
    int t = blockIdx.x * blockDim.x + threadIdx.x;
    int stride = gridDim.x * blockDim.x;
    int cn = 0, cp = 0;
    for (int i = t; i < E; i += stride) {
        float x = ep[i];
        if (x <= 0.f) cn++; else cp++;
    }
    cn = __reduce_add_sync(0xffffffffu, cn);
    cp = __reduce_add_sync(0xffffffffu, cp);
    if ((threadIdx.x & 31) == 0) {
        atomicAdd(&g_cnt[0], cn);
        atomicAdd(&g_cnt[1], cp);
    }
}

__global__ void k_init_select() {
    long long nn = g_cnt[0], np = g_cnt[1];
    double idxn = 0.2 * (double)(nn - 1);
    double fln = floor(idxn);
    g_frac[0] = idxn - fln;
    long long lon = (long long)fln;
    long long hin = lon + 1; if (hin > nn - 1) hin = nn - 1;
    g_rank[0] = (int)lon; g_rank[1] = (int)hin;

    double idxp = 0.8 * (double)(np - 1);
    double flp = floor(idxp);
    g_frac[1] = idxp - flp;
    long long lop = (long long)flp;
    long long hip = lop + 1; if (hip > np - 1) hip = np - 1;
    g_rank[2] = (int)lop; g_rank[3] = (int)hip;

    for (int t = 0; t < 4; t++) g_prefix[t] = 0u;
}

__global__ void k_hist(const float* __restrict__ ep, int E, int shift) {
    __shared__ unsigned sh[1024];
    for (int i = threadIdx.x; i < 1024; i += blockDim.x) sh[i] = 0;
    __syncthreads();
    unsigned hm = (shift == 24) ? 0u : (0xFFFFFFFFu << (shift + 8));
    unsigned p0 = g_prefix[0], p1 = g_prefix[1], p2 = g_prefix[2], p3 = g_prefix[3];
    int t = blockIdx.x * blockDim.x + threadIdx.x;
    int stride = gridDim.x * blockDim.x;
    for (int i = t; i < E; i += stride) {
        float x = ep[i];
        unsigned key = f2u(x);
        unsigned bin = (key >> shift) & 255u;
        unsigned kh = key & hm;
        if (x <= 0.f) {
            if (kh == p0) atomicAdd(&sh[bin], 1u);
            if (kh == p1) atomicAdd(&sh[256 + bin], 1u);
        } else {
            if (kh == p2) atomicAdd(&sh[512 + bin], 1u);
            if (kh == p3) atomicAdd(&sh[768 + bin], 1u);
        }
    }
    __syncthreads();
    for (int i = threadIdx.x; i < 1024; i += blockDim.x)
        if (sh[i]) atomicAdd(&g_hist[i], sh[i]);
}

__global__ void k_pick(int shift) {
    int tid = threadIdx.x;
    if (tid < 4) {
        int r = g_rank[tid];
        unsigned pref = g_prefix[tid];
        const unsigned* h = &g_hist[tid * 256];
        for (int b = 0; b < 256; b++) {
            unsigned c = h[b];
            if ((unsigned)r < c) { pref |= ((unsigned)b << shift); break; }
            r -= (int)c;
        }
        g_prefix[tid] = pref;
        g_rank[tid] = r;
    }
    __syncthreads();
    for (int i = tid; i < 1024; i += blockDim.x) g_hist[i] = 0;
}

__global__ void k_finalize() {
    float vlo = u2f(g_prefix[0]), vhi = u2f(g_prefix[1]);
    g_thr[0] = (float)((double)vlo + g_frac[0] * ((double)vhi - (double)vlo));
    vlo = u2f(g_prefix[2]); vhi = u2f(g_prefix[3]);
    g_thr[1] = (float)((double)vlo + g_frac[1] * ((double)vhi - (double)vlo));
}

// ---------------- classify + degrees -----------------------------------------
__global__ void k_classify(const float* __restrict__ ep, const int* __restrict__ dst, int E) {
    int i = blockIdx.x * blockDim.x + threadIdx.x;
    if (i >= E) return;
    float x = ep[i];
    float tn = g_thr[0], tp = g_thr[1];
    int c = (x > tp) ? 0 : ((x < tn) ? 2 : 1);   // 0=pos, 1=unk, 2=neg
    g_cls[i] = (unsigned char)c;
    atomicAdd(&g_deg[c * NN + dst[i]], 1);
}

__global__ void k_dinv() {
    int i = blockIdx.x * blockDim.x + threadIdx.x;
    if (i >= 3 * NN) return;
    int d = g_deg[i];
    if (d < 1) d = 1;
    g_dinv[i] = 1.0f / sqrtf((float)d);
}

// ---------------- SpMV: one fused pass over all edges / all families ----------
__global__ void k_zero_agg() {
    int t = blockIdx.x * blockDim.x + threadIdx.x;
    int stride = gridDim.x * blockDim.x;
    float4 z = make_float4(0.f, 0.f, 0.f, 0.f);
    for (int i = t; i < 3 * NN * (HF / 4); i += stride)
        ((float4*)g_agg)[i] = z;
}

__global__ void __launch_bounds__(256) k_spmv_all(const float* __restrict__ fbase, int perFam,
                       const int* __restrict__ src, const int* __restrict__ dst, int E) {
    int t = blockIdx.x * blockDim.x + threadIdx.x;
    int e = t >> 4, lane = t & 15;
    if (e >= E) return;
    int s = 0, d = 0, c = 0; float sc = 0.f;
    if (lane == 0) {
        s = src[e]; d = dst[e]; c = (int)g_cls[e];
        sc = g_dinv[c * NN + s];
    }
    s  = __shfl_sync(0xffffffffu, s,  0, 16);
    d  = __shfl_sync(0xffffffffu, d,  0, 16);
    c  = __shfl_sync(0xffffffffu, c,  0, 16);
    sc = __shfl_sync(0xffffffffu, sc, 0, 16);
    const float* f = fbase + (perFam ? ((size_t)c * NN * HF) : 0);
    float4 v = *(const float4*)(f + (size_t)s * HF + lane * 4);
    v.x *= sc; v.y *= sc; v.z *= sc; v.w *= sc;
    red4(g_agg + ((size_t)c * NN + d) * HF + lane * 4, v);
}

// L1_c = h - agg_c*dinv_c, all families at once
__global__ void __launch_bounds__(256) k_combine1_all() {
    int i = blockIdx.x * blockDim.x + threadIdx.x;
    if (i >= NN * (HF / 4)) return;
    int row = i >> 4;
    float4 h = ((const float4*)g_h)[i];
    #pragma unroll
    for (int c = 0; c < 3; c++) {
        float4 a = ((const float4*)g_agg)[(size_t)c * NN * (HF / 4) + i];
        float dv = g_dinv[c * NN + row];
        float4 o;
        o.x = h.x - a.x * dv; o.y = h.y - a.y * dv;
        o.z = h.z - a.z * dv; o.w = h.w - a.w * dv;
        ((float4*)g_L1)[(size_t)c * NN * (HF / 4) + i] = o;
    }
}

// slice_c = C0*h + C1*L1_c + C2*(L1_c - agg_c*dinv_c)  -> g_hf[:, c*64 : c*64+64]
__global__ void __launch_bounds__(256) k_combine2_all() {
    int i = blockIdx.x * blockDim.x + threadIdx.x;
    if (i >= NN * (HF / 4)) return;
    int row = i >> 4, j4 = i & 15;
    const float C0[3] = {0.f, 0.f, 3.f};
    const float C1[3] = {0.f, 3.f, -3.f};
    const float C2[3] = {0.75f, -1.5f, 0.75f};
    float4 h = ((const float4*)g_h)[i];
    #pragma unroll
    for (int c = 0; c < 3; c++) {
        float4 l1 = ((const float4*)g_L1)[(size_t)c * NN * (HF / 4) + i];
        float4 a  = ((const float4*)g_agg)[(size_t)c * NN * (HF / 4) + i];
        float dv = g_dinv[c * NN + row];
        float4 o; float l2;
        l2 = l1.x - a.x * dv; o.x = C0[c] * h.x + C1[c] * l1.x + C2[c] * l2;
        l2 = l1.y - a.y * dv; o.y = C0[c] * h.y + C1[c] * l1.y + C2[c] * l2;
        l2 = l1.z - a.z * dv; o.z = C0[c] * h.z + C1[c] * l1.z + C2[c] * l2;
        l2 = l1.w - a.w * dv; o.w = C0[c] * h.w + C1[c] * l1.w + C2[c] * l2;
        ((float4*)g_hf)[(size_t)row * (HF3 / 4) + c * 16 + j4] = o;
    }
}

// ---------------- GEMM: out = relu(A[M,K] @ W[K,64] + b), f32x2 packed FMA ----
// tile 64x64, 256 threads, thread = 2 rows x 8 cols, K chunked by 64.
template <int K>
__global__ void __launch_bounds__(256) k_gemm(const float* __restrict__ A, const float* __restrict__ W,
                       const float* __restrict__ bias, float* __restrict__ out, int M) {
    __shared__ float sA[64 * 65];
    __shared__ float sW[64 * 64];
    int tid = threadIdx.x;
    int r2 = tid >> 3;               // 0..31 -> rows 2*r2, 2*r2+1
    int c8 = (tid & 7) * 8;          // 0..56
    int row0 = r2 * 2, row1 = row0 + 1;
    float4 bA = *(const float4*)&bias[c8];
    float4 bB = *(const float4*)&bias[c8 + 4];

    for (int tile = blockIdx.x * 64; tile < M; tile += gridDim.x * 64) {
        ull a00 = 0, a01 = 0, a02 = 0, a03 = 0;
        ull a10 = 0, a11 = 0, a12 = 0, a13 = 0;
        for (int ch = 0; ch < K; ch += 64) {
            __syncthreads();
            // stage A chunk [64 rows][64 k], padded rows
            #pragma unroll
            for (int idx = tid; idx < 64 * 16; idx += 256) {
                int r = idx >> 4, k4 = idx & 15;
                int gr = tile + r;
                float4 v = make_float4(0.f, 0.f, 0.f, 0.f);
                if (gr < M) v = *(const float4*)&A[(size_t)gr * K + ch + k4 * 4];
                float* p = &sA[r * 65 + k4 * 4];
                p[0] = v.x; p[1] = v.y; p[2] = v.z; p[3] = v.w;
            }
            // stage W chunk [64 k][64 cols]
            #pragma unroll
            for (int idx = tid; idx < 64 * 16; idx += 256)
                ((float4*)sW)[idx] = ((const float4*)(W + ch * 64))[idx];
            __syncthreads();
            #pragma unroll 8
            for (int k = 0; k < 64; k++) {
                ull aa0 = packdup(sA[row0 * 65 + k]);
                ull aa1 = packdup(sA[row1 * 65 + k]);
                const float* wr = &sW[k * 64 + c8];
                ulonglong2 wA = *(const ulonglong2*)wr;
                ulonglong2 wB = *(const ulonglong2*)(wr + 4);
                FMA2(a00, aa0, wA.x); FMA2(a01, aa0, wA.y);
                FMA2(a02, aa0, wB.x); FMA2(a03, aa0, wB.y);
                FMA2(a10, aa1, wA.x); FMA2(a11, aa1, wA.y);
                FMA2(a12, aa1, wB.x); FMA2(a13, aa1, wB.y);
            }
        }
        int gr0 = tile + row0, gr1 = tile + row1;
        if (gr0 < M) {
            float2 u0 = unpack2(a00), u1 = unpack2(a01), u2 = unpack2(a02), u3 = unpack2(a03);
            float4 oA, oB;
            oA.x = fmaxf(u0.x + bA.x, 0.f); oA.y = fmaxf(u0.y + bA.y, 0.f);
            oA.z = fmaxf(u1.x + bA.z, 0.f); oA.w = fmaxf(u1.y + bA.w, 0.f);
            oB.x = fmaxf(u2.x + bB.x, 0.f); oB.y = fmaxf(u2.y + bB.y, 0.f);
            oB.z = fmaxf(u3.x + bB.z, 0.f); oB.w = fmaxf(u3.y + bB.w, 0.f);
            *(float4*)&out[(size_t)gr0 * 64 + c8]     = oA;
            *(float4*)&out[(size_t)gr0 * 64 + c8 + 4] = oB;
        }
        if (gr1 < M) {
            float2 u0 = unpack2(a10), u1 = unpack2(a11), u2 = unpack2(a12), u3 = unpack2(a13);
            float4 oA, oB;
            oA.x = fmaxf(u0.x + bA.x, 0.f); oA.y = fmaxf(u0.y + bA.y, 0.f);
            oA.z = fmaxf(u1.x + bA.z, 0.f); oA.w = fmaxf(u1.y + bA.w, 0.f);
            oB.x = fmaxf(u2.x + bB.x, 0.f); oB.y = fmaxf(u2.y + bB.y, 0.f);
            oB.z = fmaxf(u3.x + bB.z, 0.f); oB.w = fmaxf(u3.y + bB.w, 0.f);
            *(float4*)&out[(size_t)gr1 * 64 + c8]     = oA;
            *(float4*)&out[(size_t)gr1 * 64 + c8 + 4] = oB;
        }
    }
}

// ---------------- launch ------------------------------------------------------
extern "C" void kernel_launch(void* const* d_in, const int* in_sizes, int n_in,
                              void* d_out, int out_size) {
    const float* feat = (const float*)d_in[0];
    const float* ep   = (const float*)d_in[1];
    const int*   src  = (const int*)d_in[2];
    const int*   dst  = (const int*)d_in[3];
    const float* W1   = (const float*)d_in[4];
    const float* b1   = (const float*)d_in[5];
    const float* W2   = (const float*)d_in[6];
    const float* b2   = (const float*)d_in[7];
    const float* W3   = (const float*)d_in[8];
    const float* b3   = (const float*)d_in[9];
    float* out = (float*)d_out;
    int E = in_sizes[1];
    int M = NN;

    float *p_h, *p_L1, *p_hf;
    cudaGetSymbolAddress((void**)&p_h,  g_h);
    cudaGetSymbolAddress((void**)&p_L1, g_L1);
    cudaGetSymbolAddress((void**)&p_hf, g_hf);

    // 1) thresholds via 4-pass radix select (device-side)
    k_init<<<256, 256>>>();
    k_count<<<512, 256>>>(ep, E);
    k_init_select<<<1, 1>>>();
    for (int shift = 24; shift >= 0; shift -= 8) {
        k_hist<<<1024, 256>>>(ep, E, shift);
        k_pick<<<1, 256>>>(shift);
    }
    k_finalize<<<1, 1>>>();

    // 2) classify edges + degrees + dinv
    k_classify<<<(E + 255) / 256, 256>>>(ep, dst, E);
    k_dinv<<<(3 * NN + 255) / 256, 256>>>();

    // 3) MLP: h = relu(relu(feat@W1+b1)@W2+b2)   (g_L1 used as scratch)
    int gtiles = (M + 63) / 64;
    k_gemm<128><<<gtiles, 256>>>(feat, W1, b1, p_L1, M);
    k_gemm<64><<<gtiles, 256>>>(p_L1, W2, b2, p_h, M);

    // 4) Laplacian powers, all families fused per round
    int spmv_blocks = (E * 16 + 255) / 256;
    int elem_blocks = (NN * (HF / 4) + 255) / 256;
    k_zero_agg<<<2048, 256>>>();
    k_spmv_all<<<spmv_blocks, 256>>>(p_h, 0, src, dst, E);
    k_combine1_all<<<elem_blocks, 256>>>();
    k_zero_agg<<<2048, 256>>>();
    k_spmv_all<<<spmv_blocks, 256>>>(p_L1, 1, src, dst, E);
    k_combine2_all<<<elem_blocks, 256>>>();

    // 5) out = relu(hfinal @ W3 + b3)
    k_gemm<192><<<gtiles, 256>>>(p_hf, W3, b3, out, M);
}

// round 9
// speedup vs baseline: 1.6986x; 1.1502x over previous
#include <cuda_runtime.h>
#include <cstdint>
#include <math.h>

#define NN 100000          // nodes
#define EE 1600000         // edges (max)
#define HF 64              // hidden feats
#define HF3 192            // (D+1)*HF
#define NG (3 * NN)        // (fam,node) groups
typedef unsigned long long ull;

// ---------------- scratch (device globals; no allocations allowed) ----------
__device__ __align__(128) float g_h  [NN * HF];        // MLP output h
__device__ __align__(128) float g_L1 [3 * NN * HF];    // per-family L^1 h (also layer-1 scratch)
__device__ __align__(128) float g_hf [NN * HF3];       // concatenated features
__device__ float g_dinv[NG];
__device__ int   g_deg [NG];
__device__ int   g_off [NG];           // CSR offsets (exclusive scan of deg)
__device__ int   g_cur [NG];           // fill cursors
__device__ int   g_bsum[256];          // scan block sums
__device__ int   g_esrc[EE];           // CSR: src node per slot
__device__ float g_esc [EE];           // CSR: dinv[fam,src] per slot
__device__ unsigned char g_cls[EE];
__device__ unsigned int g_hist[4 * 256];
__device__ int g_cnt[2];
__device__ unsigned int g_prefix[4];
__device__ int g_rank[4];
__device__ double g_frac[2];
__device__ float g_thr[2];

// ---------------- helpers ----------------------------------------------------
__device__ __forceinline__ unsigned f2u(float f) {
    unsigned u = __float_as_uint(f);
    return (u & 0x80000000u) ? ~u : (u ^ 0x80000000u);
}
__device__ __forceinline__ float u2f(unsigned k) {
    unsigned u = (k & 0x80000000u) ? (k ^ 0x80000000u) : ~k;
    return __uint_as_float(u);
}
#define FMA2(acc, a, w) asm("fma.rn.f32x2 %0, %1, %2, %0;" : "+l"(acc) : "l"(a), "l"(w))
__device__ __forceinline__ ull packdup(float a) {
    ull r;
    asm("mov.b64 %0, {%1, %1};" : "=l"(r) : "r"(__float_as_uint(a)));
    return r;
}
__device__ __forceinline__ float2 unpack2(ull v) {
    unsigned lo, hi;
    asm("mov.b64 {%0, %1}, %2;" : "=r"(lo), "=r"(hi) : "l"(v));
    return make_float2(__uint_as_float(lo), __uint_as_float(hi));
}

// ---------------- init / quantile --------------------------------------------
__global__ void k_init() {
    int t = blockIdx.x * blockDim.x + threadIdx.x;
    int stride = gridDim.x * blockDim.x;
    for (int i = t; i < 4 * 256; i += stride) g_hist[i] = 0;
    for (int i = t; i < NG; i += stride) g_deg[i] = 0;
    if (t < 2) g_cnt[t] = 0;
}

__global__ void k_count(const float* __restrict__ ep, int E) {
    int t = blockIdx.x * blockDim.x + threadIdx.x;
    int stride = gridDim.x * blockDim.x;
    int cn = 0, cp = 0;
    for (int i = t; i < E; i += stride) {
        float x = ep[i];
        if (x <= 0.f) cn++; else cp++;
    }
    cn = __reduce_add_sync(0xffffffffu, cn);
    cp = __reduce_add_sync(0xffffffffu, cp);
    if ((threadIdx.x & 31) == 0) {
        atomicAdd(&g_cnt[0], cn);
        atomicAdd(&g_cnt[1], cp);
    }
}

__global__ void k_init_select() {
    long long nn = g_cnt[0], np = g_cnt[1];
    double idxn = 0.2 * (double)(nn - 1);
    double fln = floor(idxn);
    g_frac[0] = idxn - fln;
    long long lon = (long long)fln;
    long long hin = lon + 1; if (hin > nn - 1) hin = nn - 1;
    g_rank[0] = (int)lon; g_rank[1] = (int)hin;

    double idxp = 0.8 * (double)(np - 1);
    double flp = floor(idxp);
    g_frac[1] = idxp - flp;
    long long lop = (long long)flp;
    long long hip = lop + 1; if (hip > np - 1) hip = np - 1;
    g_rank[2] = (int)lop; g_rank[3] = (int)hip;

    for (int t = 0; t < 4; t++) g_prefix[t] = 0u;
}

__global__ void k_hist(const float* __restrict__ ep, int E, int shift) {
    __shared__ unsigned sh[1024];
    for (int i = threadIdx.x; i < 1024; i += blockDim.x) sh[i] = 0;
    __syncthreads();
    unsigned hm = (shift == 24) ? 0u : (0xFFFFFFFFu << (shift + 8));
    unsigned p0 = g_prefix[0], p1 = g_prefix[1], p2 = g_prefix[2], p3 = g_prefix[3];
    int t = blockIdx.x * blockDim.x + threadIdx.x;
    int stride = gridDim.x * blockDim.x;
    for (int i = t; i < E; i += stride) {
        float x = ep[i];
        unsigned key = f2u(x);
        unsigned bin = (key >> shift) & 255u;
        unsigned kh = key & hm;
        if (x <= 0.f) {
            if (kh == p0) atomicAdd(&sh[bin], 1u);
            if (kh == p1) atomicAdd(&sh[256 + bin], 1u);
        } else {
            if (kh == p2) atomicAdd(&sh[512 + bin], 1u);
            if (kh == p3) atomicAdd(&sh[768 + bin], 1u);
        }
    }
    __syncthreads();
    for (int i = threadIdx.x; i < 1024; i += blockDim.x)
        if (sh[i]) atomicAdd(&g_hist[i], sh[i]);
}

__global__ void k_pick(int shift) {
    int tid = threadIdx.x;
    if (tid < 4) {
        int r = g_rank[tid];
        unsigned pref = g_prefix[tid];
        const unsigned* h = &g_hist[tid * 256];
        for (int b = 0; b < 256; b++) {
            unsigned c = h[b];
            if ((unsigned)r < c) { pref |= ((unsigned)b << shift); break; }
            r -= (int)c;
        }
        g_prefix[tid] = pref;
        g_rank[tid] = r;
    }
    __syncthreads();
    for (int i = tid; i < 1024; i += blockDim.x) g_hist[i] = 0;
}

__global__ void k_finalize() {
    float vlo = u2f(g_prefix[0]), vhi = u2f(g_prefix[1]);
    g_thr[0] = (float)((double)vlo + g_frac[0] * ((double)vhi - (double)vlo));
    vlo = u2f(g_prefix[2]); vhi = u2f(g_prefix[3]);
    g_thr[1] = (float)((double)vlo + g_frac[1] * ((double)vhi - (double)vlo));
}

// ---------------- classify + degrees -----------------------------------------
__global__ void k_classify(const float* __restrict__ ep, const int* __restrict__ dst, int E) {
    int i = blockIdx.x * blockDim.x + threadIdx.x;
    if (i >= E) return;
    float x = ep[i];
    float tn = g_thr[0], tp = g_thr[1];
    int c = (x > tp) ? 0 : ((x < tn) ? 2 : 1);   // 0=pos, 1=unk, 2=neg
    g_cls[i] = (unsigned char)c;
    atomicAdd(&g_deg[c * NN + dst[i]], 1);
}

__global__ void k_dinv() {
    int i = blockIdx.x * blockDim.x + threadIdx.x;
    if (i >= NG) return;
    int d = g_deg[i];
    if (d < 1) d = 1;
    g_dinv[i] = 1.0f / sqrtf((float)d);
}

// ---------------- exclusive scan of g_deg -> g_off ----------------------------
// chunk = 2048 per block (256 thr x 8)
__global__ void __launch_bounds__(256) k_scan1() {
    __shared__ int ssum[256];
    int tid = threadIdx.x;
    int base = blockIdx.x * 2048 + tid * 8;
    int v[8]; int s = 0;
    #pragma unroll
    for (int i = 0; i < 8; i++) {
        v[i] = (base + i < NG) ? g_deg[base + i] : 0;
        s += v[i];
    }
    ssum[tid] = s;
    __syncthreads();
    // Hillis-Steele inclusive scan on ssum
    #pragma unroll
    for (int d = 1; d < 256; d <<= 1) {
        int t = (tid >= d) ? ssum[tid - d] : 0;
        __syncthreads();
        ssum[tid] += t;
        __syncthreads();
    }
    int run = ssum[tid] - s;   // exclusive prefix for this thread
    #pragma unroll
    for (int i = 0; i < 8; i++) {
        if (base + i < NG) g_off[base + i] = run;
        run += v[i];
    }
    if (tid == 255) g_bsum[blockIdx.x] = ssum[255];
}

__global__ void k_scan2(int nblk) {
    if (threadIdx.x == 0) {
        int acc = 0;
        for (int i = 0; i < nblk; i++) {
            int v = g_bsum[i];
            g_bsum[i] = acc;
            acc += v;
        }
    }
}

__global__ void k_scan3() {
    int i = blockIdx.x * blockDim.x + threadIdx.x;
    if (i >= NG) return;
    int o = g_off[i] + g_bsum[i >> 11];
    g_off[i] = o;
    g_cur[i] = o;
}

// ---------------- CSR fill ----------------------------------------------------
__global__ void k_fill(const int* __restrict__ src, const int* __restrict__ dst, int E) {
    int i = blockIdx.x * blockDim.x + threadIdx.x;
    if (i >= E) return;
    int c = (int)g_cls[i];
    int s = src[i];
    int slot = atomicAdd(&g_cur[c * NN + dst[i]], 1);
    g_esrc[slot] = s;
    g_esc[slot] = g_dinv[c * NN + s];
}

// ---------------- gather aggregation (no atomics) -----------------------------
// group = 16 lanes per (fam,node); round 1: L1 = h - dinv*sum(sc*h[src])
__global__ void __launch_bounds__(256) k_aggL1() {
    int t = blockIdx.x * blockDim.x + threadIdx.x;
    int gi = t >> 4, lane = t & 15;
    if (gi >= NG) return;
    int fam = gi / NN;
    int node = gi - fam * NN;
    int o0 = g_off[gi], deg = g_deg[gi];
    float4 acc = make_float4(0.f, 0.f, 0.f, 0.f);
    for (int j = 0; j < deg; j++) {
        int s = g_esrc[o0 + j];
        float sc = g_esc[o0 + j];
        float4 v = *(const float4*)(g_h + (size_t)s * HF + lane * 4);
        acc.x = fmaf(sc, v.x, acc.x); acc.y = fmaf(sc, v.y, acc.y);
        acc.z = fmaf(sc, v.z, acc.z); acc.w = fmaf(sc, v.w, acc.w);
    }
    float dv = g_dinv[gi];
    float4 h = *(const float4*)(g_h + (size_t)node * HF + lane * 4);
    float4 o;
    o.x = h.x - dv * acc.x; o.y = h.y - dv * acc.y;
    o.z = h.z - dv * acc.z; o.w = h.w - dv * acc.w;
    *(float4*)(g_L1 + ((size_t)fam * NN + node) * HF + lane * 4) = o;
}

// round 2: slice_fam = C0*h + C1*L1 + C2*(L1 - dinv*sum(sc*L1[src]))
__global__ void __launch_bounds__(256) k_aggHF() {
    const float C0[3] = {0.f, 0.f, 3.f};
    const float C1[3] = {0.f, 3.f, -3.f};
    const float C2[3] = {0.75f, -1.5f, 0.75f};
    int t = blockIdx.x * blockDim.x + threadIdx.x;
    int gi = t >> 4, lane = t & 15;
    if (gi >= NG) return;
    int fam = gi / NN;
    int node = gi - fam * NN;
    int o0 = g_off[gi], deg = g_deg[gi];
    const float* f = g_L1 + (size_t)fam * NN * HF;
    float4 acc = make_float4(0.f, 0.f, 0.f, 0.f);
    for (int j = 0; j < deg; j++) {
        int s = g_esrc[o0 + j];
        float sc = g_esc[o0 + j];
        float4 v = *(const float4*)(f + (size_t)s * HF + lane * 4);
        acc.x = fmaf(sc, v.x, acc.x); acc.y = fmaf(sc, v.y, acc.y);
        acc.z = fmaf(sc, v.z, acc.z); acc.w = fmaf(sc, v.w, acc.w);
    }
    float dv = g_dinv[gi];
    float4 l1 = *(const float4*)(f + (size_t)node * HF + lane * 4);
    float4 h = *(const float4*)(g_h + (size_t)node * HF + lane * 4);
    float c0 = C0[fam], c1 = C1[fam], c2 = C2[fam];
    float4 o; float l2;
    l2 = l1.x - dv * acc.x; o.x = c0 * h.x + c1 * l1.x + c2 * l2;
    l2 = l1.y - dv * acc.y; o.y = c0 * h.y + c1 * l1.y + c2 * l2;
    l2 = l1.z - dv * acc.z; o.z = c0 * h.z + c1 * l1.z + c2 * l2;
    l2 = l1.w - dv * acc.w; o.w = c0 * h.w + c1 * l1.w + c2 * l2;
    *(float4*)(g_hf + (size_t)node * HF3 + fam * HF + lane * 4) = o;
}

// ---------------- GEMM: out = relu(A[M,K] @ W[K,64] + b), f32x2 packed FMA ----
template <int K>
__global__ void __launch_bounds__(256) k_gemm(const float* __restrict__ A, const float* __restrict__ W,
                       const float* __restrict__ bias, float* __restrict__ out, int M) {
    __shared__ float sA[64 * 65];
    __shared__ float sW[64 * 64];
    int tid = threadIdx.x;
    int r2 = tid >> 3;
    int c8 = (tid & 7) * 8;
    int row0 = r2 * 2, row1 = row0 + 1;
    float4 bA = *(const float4*)&bias[c8];
    float4 bB = *(const float4*)&bias[c8 + 4];

    for (int tile = blockIdx.x * 64; tile < M; tile += gridDim.x * 64) {
        ull a00 = 0, a01 = 0, a02 = 0, a03 = 0;
        ull a10 = 0, a11 = 0, a12 = 0, a13 = 0;
        for (int ch = 0; ch < K; ch += 64) {
            __syncthreads();
            #pragma unroll
            for (int idx = tid; idx < 64 * 16; idx += 256) {
                int r = idx >> 4, k4 = idx & 15;
                int gr = tile + r;
                float4 v = make_float4(0.f, 0.f, 0.f, 0.f);
                if (gr < M) v = *(const float4*)&A[(size_t)gr * K + ch + k4 * 4];
                float* p = &sA[r * 65 + k4 * 4];
                p[0] = v.x; p[1] = v.y; p[2] = v.z; p[3] = v.w;
            }
            #pragma unroll
            for (int idx = tid; idx < 64 * 16; idx += 256)
                ((float4*)sW)[idx] = ((const float4*)(W + ch * 64))[idx];
            __syncthreads();
            #pragma unroll 8
            for (int k = 0; k < 64; k++) {
                ull aa0 = packdup(sA[row0 * 65 + k]);
                ull aa1 = packdup(sA[row1 * 65 + k]);
                const float* wr = &sW[k * 64 + c8];
                ulonglong2 wA = *(const ulonglong2*)wr;
                ulonglong2 wB = *(const ulonglong2*)(wr + 4);
                FMA2(a00, aa0, wA.x); FMA2(a01, aa0, wA.y);
                FMA2(a02, aa0, wB.x); FMA2(a03, aa0, wB.y);
                FMA2(a10, aa1, wA.x); FMA2(a11, aa1, wA.y);
                FMA2(a12, aa1, wB.x); FMA2(a13, aa1, wB.y);
            }
        }
        int gr0 = tile + row0, gr1 = tile + row1;
        if (gr0 < M) {
            float2 u0 = unpack2(a00), u1 = unpack2(a01), u2 = unpack2(a02), u3 = unpack2(a03);
            float4 oA, oB;
            oA.x = fmaxf(u0.x + bA.x, 0.f); oA.y = fmaxf(u0.y + bA.y, 0.f);
            oA.z = fmaxf(u1.x + bA.z, 0.f); oA.w = fmaxf(u1.y + bA.w, 0.f);
            oB.x = fmaxf(u2.x + bB.x, 0.f); oB.y = fmaxf(u2.y + bB.y, 0.f);
            oB.z = fmaxf(u3.x + bB.z, 0.f); oB.w = fmaxf(u3.y + bB.w, 0.f);
            *(float4*)&out[(size_t)gr0 * 64 + c8]     = oA;
            *(float4*)&out[(size_t)gr0 * 64 + c8 + 4] = oB;
        }
        if (gr1 < M) {
            float2 u0 = unpack2(a10), u1 = unpack2(a11), u2 = unpack2(a12), u3 = unpack2(a13);
            float4 oA, oB;
            oA.x = fmaxf(u0.x + bA.x, 0.f); oA.y = fmaxf(u0.y + bA.y, 0.f);
            oA.z = fmaxf(u1.x + bA.z, 0.f); oA.w = fmaxf(u1.y + bA.w, 0.f);
            oB.x = fmaxf(u2.x + bB.x, 0.f); oB.y = fmaxf(u2.y + bB.y, 0.f);
            oB.z = fmaxf(u3.x + bB.z, 0.f); oB.w = fmaxf(u3.y + bB.w, 0.f);
            *(float4*)&out[(size_t)gr1 * 64 + c8]     = oA;
            *(float4*)&out[(size_t)gr1 * 64 + c8 + 4] = oB;
        }
    }
}

// ---------------- launch ------------------------------------------------------
extern "C" void kernel_launch(void* const* d_in, const int* in_sizes, int n_in,
                              void* d_out, int out_size) {
    const float* feat = (const float*)d_in[0];
    const float* ep   = (const float*)d_in[1];
    const int*   src  = (const int*)d_in[2];
    const int*   dst  = (const int*)d_in[3];
    const float* W1   = (const float*)d_in[4];
    const float* b1   = (const float*)d_in[5];
    const float* W2   = (const float*)d_in[6];
    const float* b2   = (const float*)d_in[7];
    const float* W3   = (const float*)d_in[8];
    const float* b3   = (const float*)d_in[9];
    float* out = (float*)d_out;
    int E = in_sizes[1];
    int M = NN;

    float *p_h, *p_L1, *p_hf;
    cudaGetSymbolAddress((void**)&p_h,  g_h);
    cudaGetSymbolAddress((void**)&p_L1, g_L1);
    cudaGetSymbolAddress((void**)&p_hf, g_hf);

    // 1) thresholds via 4-pass radix select (device-side)
    k_init<<<256, 256>>>();
    k_count<<<512, 256>>>(ep, E);
    k_init_select<<<1, 1>>>();
    for (int shift = 24; shift >= 0; shift -= 8) {
        k_hist<<<1024, 256>>>(ep, E, shift);
        k_pick<<<1, 256>>>(shift);
    }
    k_finalize<<<1, 1>>>();

    // 2) classify + degrees + dinv
    k_classify<<<(E + 255) / 256, 256>>>(ep, dst, E);
    k_dinv<<<(NG + 255) / 256, 256>>>();

    // 3) CSR build: scan degrees, fill buckets
    int nscan = (NG + 2047) / 2048;
    k_scan1<<<nscan, 256>>>();
    k_scan2<<<1, 32>>>(nscan);
    k_scan3<<<(NG + 255) / 256, 256>>>();
    k_fill<<<(E + 255) / 256, 256>>>(src, dst, E);

    // 4) MLP: h = relu(relu(feat@W1+b1)@W2+b2)   (g_L1 used as scratch)
    int gtiles = (M + 63) / 64;
    k_gemm<128><<<gtiles, 256>>>(feat, W1, b1, p_L1, M);
    k_gemm<64><<<gtiles, 256>>>(p_L1, W2, b2, p_h, M);

    // 5) Laplacian powers via CSR gather (atomic-free), combines fused
    int agg_blocks = (NG * 16 + 255) / 256;
    k_aggL1<<<agg_blocks, 256>>>();
    k_aggHF<<<agg_blocks, 256>>>();

    // 6) out = relu(hfinal @ W3 + b3)
    k_gemm<192><<<gtiles, 256>>>(p_hf, W3, b3, out, M);
}